// round 2
// baseline (speedup 1.0000x reference)
#include <cuda_runtime.h>
#include <cstdint>
#include <cstddef>

// Problem dims (fixed by reference)
#define Bb 256
#define Tt 512
#define Dd 64
#define Ll 32
#define Hh 128
#define G4 512   // 4*H

// ---------------- scratch (device globals; no allocation allowed) ----------
__device__ float g_pre[(size_t)Bb * Tt * G4];   // 268 MB: pre-activations
__device__ float g_stat[Bb * G4];               // static part: x_static@Wzh^T + b

// ---------------- math helpers ---------------------------------------------
__device__ __forceinline__ float sigf(float x) {
    return __fdividef(1.0f, 1.0f + __expf(-x));
}
__device__ __forceinline__ float tanhf_fast(float x) {
    x = fminf(20.0f, fmaxf(-20.0f, x));
    float e = __expf(-2.0f * x);
    return __fdividef(1.0f - e, 1.0f + e);
}

// ============================================================================
// Kernel 1: g_stat[b][g] = sum_l x_static[b][l] * W_zh[g][l] + b[g]
// ============================================================================
__global__ __launch_bounds__(512) void static_kernel(
    const float* __restrict__ xs, const float* __restrict__ Wzh,
    const float* __restrict__ bvec)
{
    __shared__ float xrow[Ll];
    int bb = blockIdx.x;
    int g  = threadIdx.x;
    if (g < Ll) xrow[g] = xs[bb * Ll + g];
    __syncthreads();
    float acc = bvec[g];
    const float* w = Wzh + g * Ll;
#pragma unroll
    for (int l = 0; l < Ll; l++) acc += xrow[l] * w[l];
    g_stat[bb * G4 + g] = acc;
}

// ============================================================================
// Kernel 2: g_pre[m][n] = sum_k x_dyn[m][k]*W_ih[n][k] + g_stat[b][n]
//   M = B*T = 131072, N = 512, K = 64.  Tiles: 64 (M) x 128 (N), K full.
//   Shared row-major with pad 65 (odd stride -> conflict-free strided reads).
// ============================================================================
#define PRE_MT 64
#define PRE_NT 128
#define PRE_PAD 65
#define PRE_SMEM (((PRE_MT + PRE_NT) * PRE_PAD) * 4)   // 49920 bytes

__global__ __launch_bounds__(256) void pre_kernel(
    const float* __restrict__ xd, const float* __restrict__ Wih)
{
    extern __shared__ float sm[];
    float* xsm = sm;                      // [64][65]
    float* wsm = sm + PRE_MT * PRE_PAD;   // [128][65]

    int t  = threadIdx.x;
    int m0 = blockIdx.x * PRE_MT;
    int n0 = blockIdx.y * PRE_NT;

    // Fill xs (coalesced float4 global loads, scalar STS)
    {
        const float4* xg = (const float4*)(xd + (size_t)m0 * Dd);
        for (int i = t; i < PRE_MT * (Dd / 4); i += 256) {
            int row = i >> 4, dq = i & 15;
            float4 v = xg[row * 16 + dq];
            float* dst = xsm + row * PRE_PAD + dq * 4;
            dst[0] = v.x; dst[1] = v.y; dst[2] = v.z; dst[3] = v.w;
        }
    }
    {
        const float4* wg = (const float4*)(Wih + (size_t)n0 * Dd);
        for (int i = t; i < PRE_NT * (Dd / 4); i += 256) {
            int row = i >> 4, dq = i & 15;
            float4 v = wg[row * 16 + dq];
            float* dst = wsm + row * PRE_PAD + dq * 4;
            dst[0] = v.x; dst[1] = v.y; dst[2] = v.z; dst[3] = v.w;
        }
    }
    __syncthreads();

    int tn = t & 15;       // n fragment: n = tn + 16*jj  (interleaved)
    int tm = t >> 4;       // m fragment: m = tm + 16*ii

    float acc[4][8];
#pragma unroll
    for (int i = 0; i < 4; i++)
#pragma unroll
        for (int jj = 0; jj < 8; jj++) acc[i][jj] = 0.0f;

#pragma unroll 8
    for (int k = 0; k < Dd; k++) {
        float a[4], b[8];
#pragma unroll
        for (int i = 0; i < 4; i++)  a[i]  = xsm[(tm + 16 * i) * PRE_PAD + k];
#pragma unroll
        for (int jj = 0; jj < 8; jj++) b[jj] = wsm[(tn + 16 * jj) * PRE_PAD + k];
#pragma unroll
        for (int i = 0; i < 4; i++)
#pragma unroll
            for (int jj = 0; jj < 8; jj++) acc[i][jj] += a[i] * b[jj];
    }

    // Epilogue: add static part, write pre
    int bb = m0 >> 9;   // T = 512
    const float* srow = g_stat + bb * G4 + n0;
    float sv[8];
#pragma unroll
    for (int jj = 0; jj < 8; jj++) sv[jj] = srow[tn + 16 * jj];
#pragma unroll
    for (int i = 0; i < 4; i++) {
        float* orow = g_pre + (size_t)(m0 + tm + 16 * i) * G4 + n0;
#pragma unroll
        for (int jj = 0; jj < 8; jj++) orow[tn + 16 * jj] = acc[i][jj] + sv[jj];
    }
}

// ============================================================================
// Kernel 3: persistent LSTM scan.
//   2-CTA clusters; each CTA holds one K-half of W_hh (128 KB fp32) in smem.
//   Per step: half-matvec for 4 batch rows -> DSMEM exchange of partials
//   (double-buffered) -> 1 cluster barrier -> replicated gate/state update
//   -> fused O=1 output dot (rank 0 writes).
// ============================================================================
#define NROW 4
// float offsets within dynamic smem
#define OFF_W    0                      // 16 chunks * 512 j * 4 = 32768 floats
#define OFF_H    32768                  // h[4][128]
#define OFF_RECV (OFF_H + 512)          // recv[2][4][512]
#define OFF_G    (OFF_RECV + 4096)      // g[4][512]
#define OFF_RED  (OFF_G + 2048)         // red[16]
#define SCAN_SMEM ((OFF_RED + 16) * 4)  // 157760 bytes

__global__ void __cluster_dims__(2, 1, 1) __launch_bounds__(512, 1)
scan_kernel(const float* __restrict__ Whh, const float* __restrict__ Wout,
            const float* __restrict__ bout, float* __restrict__ out)
{
    extern __shared__ float sm[];
    int tid = threadIdx.x;
    uint32_t rank;
    asm("mov.u32 %0, %%cluster_ctarank;" : "=r"(rank));
    int cid = blockIdx.x >> 1;
    int b0  = cid * NROW;

    // ---- load our K-half of W_hh into chunked float4 layout:
    // Wv[ch][j] (float4) = W_hh[j][rank*64 + ch*4 .. +3]
    for (int idx = tid; idx < 512 * 64; idx += 512) {
        int j = idx >> 6, d = idx & 63;
        sm[OFF_W + (d >> 2) * 2048 + j * 4 + (d & 3)] =
            Whh[j * 128 + (int)rank * 64 + d];
    }
    // zero h state
    sm[OFF_H + tid] = 0.0f;
    __syncthreads();

    // peer smem base for DSMEM stores
    uint32_t my32;
    asm("{ .reg .u64 t; cvta.to.shared.u64 t, %1; cvt.u32.u64 %0, t; }"
        : "=r"(my32) : "l"(sm));
    uint32_t peer32;
    uint32_t peer_rank = rank ^ 1u;
    asm("mapa.shared::cluster.u32 %0, %1, %2;"
        : "=r"(peer32) : "r"(my32), "r"(peer_rank));

    int j  = tid;             // output gate index 0..511 (matvec role)
    int r2 = tid >> 7;        // row 0..3 (update role)
    int k  = tid & 127;       // hidden index (update role)

    float cst  = 0.0f;        // cell state (registered, per (r2,k) thread)
    float wo   = Wout[k];
    float bo   = bout[0];

    const float* pre0 = g_pre + ((size_t)(b0 + 0) * Tt) * G4 + j;
    const float* pre1 = g_pre + ((size_t)(b0 + 1) * Tt) * G4 + j;
    const float* pre2 = g_pre + ((size_t)(b0 + 2) * Tt) * G4 + j;
    const float* pre3 = g_pre + ((size_t)(b0 + 3) * Tt) * G4 + j;

    uint32_t peer_recv = peer32 + (OFF_RECV + j) * 4;   // + (buf*4+r)*2048 bytes
    int hoff = (int)rank * 64;

    // make sure both CTAs finished init before any DSMEM traffic
    asm volatile("barrier.cluster.arrive.aligned;" ::: "memory");
    asm volatile("barrier.cluster.wait.aligned;" ::: "memory");

    int buf = 0;
    for (int t = 0; t < Tt; t++) {
        // issue pre loads early (consumed after the cluster barrier)
        float p0 = pre0[(size_t)t * G4];
        float p1 = pre1[(size_t)t * G4];
        float p2 = pre2[(size_t)t * G4];
        float p3 = pre3[(size_t)t * G4];

        // half matvec: acc_r = sum_d W[j][hoff+d] * h[r][hoff+d]
        float acc0 = 0.f, acc1 = 0.f, acc2 = 0.f, acc3 = 0.f;
#pragma unroll
        for (int ch = 0; ch < 16; ch++) {
            float4 w  = *(const float4*)(sm + OFF_W + (ch * 512 + j) * 4);
            float4 h0 = *(const float4*)(sm + OFF_H + 0 * 128 + hoff + ch * 4);
            float4 h1 = *(const float4*)(sm + OFF_H + 1 * 128 + hoff + ch * 4);
            float4 h2 = *(const float4*)(sm + OFF_H + 2 * 128 + hoff + ch * 4);
            float4 h3 = *(const float4*)(sm + OFF_H + 3 * 128 + hoff + ch * 4);
            acc0 += w.x * h0.x + w.y * h0.y + w.z * h0.z + w.w * h0.w;
            acc1 += w.x * h1.x + w.y * h1.y + w.z * h1.z + w.w * h1.w;
            acc2 += w.x * h2.x + w.y * h2.y + w.z * h2.z + w.w * h2.w;
            acc3 += w.x * h3.x + w.y * h3.y + w.z * h3.z + w.w * h3.w;
        }

        // send partials to peer's recv[buf][r][j]
        {
            uint32_t a = peer_recv + (uint32_t)(buf * 4) * 2048u;
            asm volatile("st.shared::cluster.f32 [%0], %1;" :: "r"(a),          "f"(acc0) : "memory");
            asm volatile("st.shared::cluster.f32 [%0], %1;" :: "r"(a + 2048u),  "f"(acc1) : "memory");
            asm volatile("st.shared::cluster.f32 [%0], %1;" :: "r"(a + 4096u),  "f"(acc2) : "memory");
            asm volatile("st.shared::cluster.f32 [%0], %1;" :: "r"(a + 6144u),  "f"(acc3) : "memory");
        }

        asm volatile("barrier.cluster.arrive.aligned;" ::: "memory");
        asm volatile("barrier.cluster.wait.aligned;" ::: "memory");

        // full gate pre-activation (own-half + peer-half is commutative ->
        // bitwise identical on both replicas), stage for the (r,k) transpose
        {
            const float* rv = sm + OFF_RECV + (buf * 4) * 512 + j;
            sm[OFF_G + 0 * 512 + j] = p0 + (acc0 + rv[0 * 512]);
            sm[OFF_G + 1 * 512 + j] = p1 + (acc1 + rv[1 * 512]);
            sm[OFF_G + 2 * 512 + j] = p2 + (acc2 + rv[2 * 512]);
            sm[OFF_G + 3 * 512 + j] = p3 + (acc3 + rv[3 * 512]);
        }
        __syncthreads();

        // state update (replicated on both CTAs)
        float gi = sm[OFF_G + r2 * 512 + k];
        float gf = sm[OFF_G + r2 * 512 + 128 + k];
        float gc = sm[OFF_G + r2 * 512 + 256 + k];
        float go = sm[OFF_G + r2 * 512 + 384 + k];
        cst = sigf(gf) * cst + sigf(gi) * tanhf_fast(gc);
        float hval = sigf(go) * tanhf_fast(cst);
        sm[OFF_H + r2 * 128 + k] = hval;

        // fused O=1 head (rank 0 only does the reduction + write)
        if (rank == 0) {
            float v = hval * wo;
            v += __shfl_down_sync(0xffffffffu, v, 16);
            v += __shfl_down_sync(0xffffffffu, v, 8);
            v += __shfl_down_sync(0xffffffffu, v, 4);
            v += __shfl_down_sync(0xffffffffu, v, 2);
            v += __shfl_down_sync(0xffffffffu, v, 1);
            if ((tid & 31) == 0) sm[OFF_RED + (tid >> 5)] = v;
        }
        __syncthreads();   // guards h_sh for next matvec + red readiness

        if (rank == 0 && tid < NROW) {
            const float* rd = sm + OFF_RED + tid * 4;
            out[(size_t)(b0 + tid) * Tt + t] = rd[0] + rd[1] + rd[2] + rd[3] + bo;
        }
        buf ^= 1;
    }
}

// ============================================================================
// launch
// ============================================================================
extern "C" void kernel_launch(void* const* d_in, const int* in_sizes, int n_in,
                              void* d_out, int out_size)
{
    const float* x_dyn = (const float*)d_in[0];
    const float* x_sta = (const float*)d_in[1];
    const float* W_ih  = (const float*)d_in[2];
    const float* W_hh  = (const float*)d_in[3];
    const float* W_zh  = (const float*)d_in[4];
    const float* bvec  = (const float*)d_in[5];
    const float* W_out = (const float*)d_in[6];
    const float* b_out = (const float*)d_in[7];
    float* out = (float*)d_out;

    (void)in_sizes; (void)n_in; (void)out_size;

    cudaFuncSetAttribute(pre_kernel,
                         cudaFuncAttributeMaxDynamicSharedMemorySize, PRE_SMEM);
    cudaFuncSetAttribute(scan_kernel,
                         cudaFuncAttributeMaxDynamicSharedMemorySize, SCAN_SMEM);

    static_kernel<<<Bb, G4>>>(x_sta, W_zh, bvec);

    dim3 pre_grid((Bb * Tt) / PRE_MT, G4 / PRE_NT);   // 2048 x 4
    pre_kernel<<<pre_grid, 256, PRE_SMEM>>>(x_dyn, W_ih);

    scan_kernel<<<128, 512, SCAN_SMEM>>>(W_hh, W_out, b_out, out);
}